// round 1
// baseline (speedup 1.0000x reference)
#include <cuda_runtime.h>
#include <math.h>

#define Bn 16
#define Cn 64
#define Hn 128
#define Wn 128
#define HWn (Hn*Wn)
#define IMG (Cn*HWn)

#define TH 16
#define TW 16
#define RS 19                       // padded smem row stride (18 used)
#define SIN_SZ (Cn*18*RS)           // 21888 floats
#define SW_SZ  (16*9*Cn)            // 9216 floats
#define SMEM_CONV ((SIN_SZ + SW_SZ + 2*Cn)*4)

// scratch: per-layer post-ReLU features (also the concat inputs)
__device__ float g_feat[4][Bn*Cn*Hn*Wn];
__device__ float g_md[4][Cn];
__device__ float g_ms[4][Cn];

// ---------------------------------------------------------------------------
// Gumbel-softmax channel mask: (1,C,NL,2). m_d = ch_mask[...,0], m_s = [...,1]
// ---------------------------------------------------------------------------
__global__ void mask_kernel(const float* __restrict__ gum,
                            const float* __restrict__ par,
                            float* __restrict__ out_tail)
{
    int c = threadIdx.x;
    if (c >= Cn) return;
#pragma unroll
    for (int l = 0; l < 4; ++l) {
        int i0 = c*8 + l*2;
        float g0 = -logf(-logf(gum[i0]));
        float g1 = -logf(-logf(gum[i0+1]));
        float l0 = par[i0]   + g0;
        float l1 = par[i0+1] + g1;
        float e  = expf(l1 - l0);
        float m0 = 1.0f/(1.0f+e);      // dense gate
        float m1 = e/(1.0f+e);         // sparse gate
        g_md[l][c] = m0;
        g_ms[l][c] = m1;
        out_tail[i0]   = m0;
        out_tail[i0+1] = m1;
    }
}

// ---------------------------------------------------------------------------
// 3x3 conv, pad 1, with fused gating + ReLU.
//  DUAL=false (layer 0):  out = relu( F * (m_s[o]*spa + m_d[o]) )
//  DUAL=true  (layer>=1): out = relu( D * m_d[o]*(1-spa) + F * spa )
//    F = conv(fea, w) ; D = conv(fea * m_d[c], w)   (uses m_d+m_s==1)
// Block: 64 och x 16x16 px tile. 512 threads: thread = 8 och x 4 px, dual acc.
// ---------------------------------------------------------------------------
template<bool DUAL>
__global__ void __launch_bounds__(512, 1)
conv_kernel(const float* __restrict__ x0, const float* __restrict__ w,
            const float* __restrict__ spa, int layer)
{
    extern __shared__ float sm[];
    float* s_in = sm;                 // [c][18][RS]
    float* s_w  = sm + SIN_SZ;        // [ci][kk][o]
    float* s_md = s_w + SW_SZ;        // [64]
    float* s_ms = s_md + Cn;          // [64]

    const float* in  = (layer == 0) ? x0 : g_feat[layer-1];
    float*       out = g_feat[layer];

    int b   = blockIdx.z;
    int ty0 = blockIdx.y * TH;
    int tx0 = blockIdx.x * TW;
    int tid = threadIdx.x;

    if (tid < Cn) { s_md[tid] = g_md[layer][tid]; s_ms[tid] = g_ms[layer][tid]; }

    // stage input tile + halo (zero-padded)
    const float* inb = in + b*IMG;
    for (int idx = tid; idx < Cn*18*18; idx += 512) {
        int c   = idx / 324;
        int r   = (idx - c*324) / 18;
        int col = idx - c*324 - r*18;
        int y = ty0 - 1 + r, x = tx0 - 1 + col;
        float v = 0.f;
        if ((unsigned)y < Hn && (unsigned)x < Wn) v = inb[(c*Hn + y)*Wn + x];
        s_in[c*(18*RS) + r*RS + col] = v;
    }

    int og    = tid >> 6;        // 0..7   (warp-uniform: warp = tid/32)
    int pg    = tid & 63;        // 0..63
    int py    = pg >> 2;         // 0..15
    int pxb   = (pg & 3) << 2;   // 0,4,8,12
    int obase = og << 3;

    float accF[8][4];
    float accD[8][4];
#pragma unroll
    for (int u = 0; u < 8; ++u)
#pragma unroll
        for (int j = 0; j < 4; ++j) { accF[u][j] = 0.f; if (DUAL) accD[u][j] = 0.f; }

    for (int cc0 = 0; cc0 < Cn; cc0 += 16) {
        __syncthreads();
        // stage weight chunk: s_w[ci][kk][o] = w[o][cc0+ci][kk]
        for (int idx = tid; idx < SW_SZ; idx += 512) {
            int o    = idx & 63;
            int rest = idx >> 6;
            int kk   = rest % 9;
            int ci   = rest / 9;
            s_w[(ci*9 + kk)*Cn + o] = w[(o*Cn + (cc0+ci))*9 + kk];
        }
        __syncthreads();

#pragma unroll 1
        for (int ci = 0; ci < 16; ++ci) {
            float mdc = DUAL ? s_md[cc0+ci] : 0.f;
            const float* sinc = s_in + (cc0+ci)*(18*RS);
#pragma unroll
            for (int kk = 0; kk < 9; ++kk) {
                const int ky = kk/3, kx = kk - (kk/3)*3;
                float wv[8];
#pragma unroll
                for (int u = 0; u < 8; ++u) wv[u] = s_w[(ci*9+kk)*Cn + obase + u];
                float iv[4];
#pragma unroll
                for (int j = 0; j < 4; ++j) iv[j] = sinc[(py+ky)*RS + pxb+kx+j];
#pragma unroll
                for (int u = 0; u < 8; ++u)
#pragma unroll
                    for (int j = 0; j < 4; ++j)
                        accF[u][j] = fmaf(wv[u], iv[j], accF[u][j]);
                if (DUAL) {
                    float ivd[4];
#pragma unroll
                    for (int j = 0; j < 4; ++j) ivd[j] = iv[j]*mdc;
#pragma unroll
                    for (int u = 0; u < 8; ++u)
#pragma unroll
                        for (int j = 0; j < 4; ++j)
                            accD[u][j] = fmaf(wv[u], ivd[j], accD[u][j]);
                }
            }
        }
    }

    // fused gating + ReLU epilogue
    float sp[4];
#pragma unroll
    for (int j = 0; j < 4; ++j)
        sp[j] = spa[b*HWn + (ty0+py)*Wn + tx0+pxb+j];

    float* outb = out + b*IMG;
#pragma unroll
    for (int u = 0; u < 8; ++u) {
        int o = obase + u;
        float md = s_md[o], ms = s_ms[o];
#pragma unroll
        for (int j = 0; j < 4; ++j) {
            float v;
            if (!DUAL) v = accF[u][j] * (ms*sp[j] + md);
            else       v = accD[u][j] * md * (1.f - sp[j]) + accF[u][j] * sp[j];
            v = fmaxf(v, 0.f);
            outb[(o*Hn + ty0+py)*Wn + tx0+pxb+j] = v;
        }
    }
}

// ---------------------------------------------------------------------------
// Final 1x1 conv over the concat: out[b,o,p] = bc[o] + sum_k wc[o,k]*cat[k,p]
// Block: 64 o x 256 px. 256 threads: thread = 8 o x 8 px (interleaved px).
// ---------------------------------------------------------------------------
__global__ void __launch_bounds__(256)
final_kernel(const float* __restrict__ wc, const float* __restrict__ bc,
             float* __restrict__ outp)
{
    __shared__ float s_wc[16*64];    // [kk][o]
    __shared__ float s_cat[16*256];  // [kk][px]

    int blk = blockIdx.x;
    int b   = blk >> 6;
    int p0  = (blk & 63) * 256;
    int tid = threadIdx.x;
    int og  = tid >> 5;
    int pg  = tid & 31;
    int obase = og << 3;

    float acc[8][8];
#pragma unroll
    for (int u = 0; u < 8; ++u)
#pragma unroll
        for (int j = 0; j < 8; ++j) acc[u][j] = 0.f;

    for (int k0 = 0; k0 < 256; k0 += 16) {
        __syncthreads();
        for (int idx = tid; idx < 16*64; idx += 256) {
            int kk = idx >> 6, o = idx & 63;
            s_wc[kk*64 + o] = wc[o*256 + k0 + kk];
        }
        int l  = k0 >> 6;
        int cb = k0 & 63;
        const float* src = g_feat[l] + (b*Cn + cb)*HWn + p0;
        for (int idx = tid; idx < 16*256; idx += 256) {
            int kk = idx >> 8, px = idx & 255;
            s_cat[kk*256 + px] = src[kk*HWn + px];
        }
        __syncthreads();
#pragma unroll
        for (int kk = 0; kk < 16; ++kk) {
            float wv[8], cv[8];
#pragma unroll
            for (int u = 0; u < 8; ++u) wv[u] = s_wc[kk*64 + obase + u];
#pragma unroll
            for (int j = 0; j < 8; ++j) cv[j] = s_cat[kk*256 + pg + 32*j];
#pragma unroll
            for (int u = 0; u < 8; ++u)
#pragma unroll
                for (int j = 0; j < 8; ++j)
                    acc[u][j] = fmaf(wv[u], cv[j], acc[u][j]);
        }
    }

#pragma unroll
    for (int u = 0; u < 8; ++u) {
        int o = obase + u;
        float bias = bc[o];
#pragma unroll
        for (int j = 0; j < 8; ++j)
            outp[(b*Cn + o)*HWn + p0 + pg + 32*j] = acc[u][j] + bias;
    }
}

// ---------------------------------------------------------------------------
extern "C" void kernel_launch(void* const* d_in, const int* in_sizes, int n_in,
                              void* d_out, int out_size)
{
    const float* x0  = (const float*)d_in[0];
    const float* spa = (const float*)d_in[1];
    const float* gum = (const float*)d_in[2];
    const float* par = (const float*)d_in[3];
    const float* w0  = (const float*)d_in[4];
    const float* w1  = (const float*)d_in[5];
    const float* w2  = (const float*)d_in[6];
    const float* w3  = (const float*)d_in[7];
    const float* wc  = (const float*)d_in[8];
    const float* bc  = (const float*)d_in[9];

    float* outp = (float*)d_out;
    float* tail = outp + (out_size - 512);   // ch_mask (1,64,4,2) after main out

    cudaFuncSetAttribute(conv_kernel<false>,
                         cudaFuncAttributeMaxDynamicSharedMemorySize, SMEM_CONV);
    cudaFuncSetAttribute(conv_kernel<true>,
                         cudaFuncAttributeMaxDynamicSharedMemorySize, SMEM_CONV);

    mask_kernel<<<1, 64>>>(gum, par, tail);

    dim3 grid(Wn/TW, Hn/TH, Bn);   // 8 x 8 x 16
    conv_kernel<false><<<grid, 512, SMEM_CONV>>>(x0, w0, spa, 0);
    conv_kernel<true ><<<grid, 512, SMEM_CONV>>>(x0, w1, spa, 1);
    conv_kernel<true ><<<grid, 512, SMEM_CONV>>>(x0, w2, spa, 2);
    conv_kernel<true ><<<grid, 512, SMEM_CONV>>>(x0, w3, spa, 3);

    final_kernel<<<Bn*64, 256>>>(wc, bc, outp);
}

// round 2
// speedup vs baseline: 1.0569x; 1.0569x over previous
#include <cuda_runtime.h>
#include <math.h>
#include <stdint.h>

typedef unsigned long long u64;

#define Bn 16
#define Cn 64
#define Hn 128
#define Wn 128
#define HWn (Hn*Wn)
#define IMG (Cn*HWn)

#define TH 8
#define TW 16
#define RS 20                   // padded smem row stride (18 used, 16B-aligned)
#define NR (TH+2)               // 10 rows incl. halo
#define CIN_STRIDE (NR*RS)      // 200 floats per channel
#define SIN_SZ (Cn*CIN_STRIDE)  // 12800 floats
#define WCHUNK 16
#define WSTRIDE 68              // padded o-stride (16B aligned, bank-spread)
#define SW_SZ (WCHUNK*9*WSTRIDE)
#define SMEM_CONV ((SIN_SZ + SW_SZ + 2*Cn)*4)

// scratch: per-layer post-ReLU features (also the concat inputs)
__device__ float g_feat[4][Bn*IMG];
__device__ float g_md[4][Cn];
__device__ float g_ms[4][Cn];

// ---------------- f32x2 packed-math helpers (sm_100+) ----------------------
__device__ __forceinline__ u64 dup2(float x){
    u64 r; asm("mov.b64 %0,{%1,%1};" : "=l"(r) : "f"(x)); return r;
}
__device__ __forceinline__ void unpk(u64 v, float& a, float& b){
    asm("mov.b64 {%0,%1},%2;" : "=f"(a), "=f"(b) : "l"(v));
}
__device__ __forceinline__ u64 ffma2(u64 a, u64 b, u64 c){
    u64 d; asm("fma.rn.f32x2 %0,%1,%2,%3;" : "=l"(d) : "l"(a), "l"(b), "l"(c)); return d;
}
__device__ __forceinline__ u64 fmul2(u64 a, u64 b){
    u64 d; asm("mul.rn.f32x2 %0,%1,%2;" : "=l"(d) : "l"(a), "l"(b)); return d;
}
__device__ __forceinline__ u64 fadd2(u64 a, u64 b){
    u64 d; asm("add.rn.f32x2 %0,%1,%2;" : "=l"(d) : "l"(a), "l"(b)); return d;
}
__device__ __forceinline__ void lds4(float&a,float&b,float&c,float&d, uint32_t addr){
    asm volatile("ld.shared.v4.f32 {%0,%1,%2,%3},[%4];"
                 : "=f"(a),"=f"(b),"=f"(c),"=f"(d) : "r"(addr));
}
__device__ __forceinline__ void lds2(float&a,float&b, uint32_t addr){
    asm volatile("ld.shared.v2.f32 {%0,%1},[%2];" : "=f"(a),"=f"(b) : "r"(addr));
}
__device__ __forceinline__ void ldsw(u64&a,u64&b, uint32_t addr){
    asm volatile("ld.shared.v2.u64 {%0,%1},[%2];" : "=l"(a),"=l"(b) : "r"(addr));
}

// ---------------------------------------------------------------------------
// Gumbel-softmax channel mask
// ---------------------------------------------------------------------------
__global__ void mask_kernel(const float* __restrict__ gum,
                            const float* __restrict__ par,
                            float* __restrict__ out_tail)
{
    int c = threadIdx.x;
    if (c >= Cn) return;
#pragma unroll
    for (int l = 0; l < 4; ++l) {
        int i0 = c*8 + l*2;
        float g0 = -logf(-logf(gum[i0]));
        float g1 = -logf(-logf(gum[i0+1]));
        float l0 = par[i0]   + g0;
        float l1 = par[i0+1] + g1;
        float e  = expf(l1 - l0);
        float m0 = 1.0f/(1.0f+e);      // dense gate
        float m1 = e/(1.0f+e);         // sparse gate
        g_md[l][c] = m0;
        g_ms[l][c] = m1;
        out_tail[i0]   = m0;
        out_tail[i0+1] = m1;
    }
}

// ---------------------------------------------------------------------------
// 3x3 conv, pad 1, fused gating + ReLU, fp32x2 packed math.
//  DUAL=false (layer 0):  out = relu( F * (m_s[o]*spa + m_d[o]) )
//  DUAL=true  (layer>=1): out = relu( D * m_d[o]*(1-spa) + F * spa )
//    Per-input-channel partial p = sum_kk w*in;  F += p;  D += m_d[ci]*p.
// Block: 64 och x 8x16 px. 512 threads: thread = 4 och (2 f32x2 pairs) x 4 px.
// ---------------------------------------------------------------------------
template<bool DUAL>
__global__ void __launch_bounds__(512, 1)
conv_kernel(const float* __restrict__ x0, const float* __restrict__ w,
            const float* __restrict__ spa, int layer)
{
    extern __shared__ float sm[];
    float* s_in = sm;                 // [c][10][RS]
    float* s_w  = sm + SIN_SZ;        // [(ci*9+kk)][WSTRIDE] holding o 0..63
    float* s_md = s_w + SW_SZ;
    float* s_ms = s_md + Cn;

    const float* in  = (layer == 0) ? x0 : g_feat[layer-1];
    float*       out = g_feat[layer];

    const int b   = blockIdx.z;
    const int ty0 = blockIdx.y * TH;
    const int tx0 = blockIdx.x * TW;
    const int tid = threadIdx.x;

    if (tid < Cn) { s_md[tid] = g_md[layer][tid]; s_ms[tid] = g_ms[layer][tid]; }

    // stage input tile + halo (zero-padded), cols 0..17 valid
    const float* inb = in + b*IMG;
#pragma unroll 1
    for (int idx = tid; idx < Cn*NR*18; idx += 512) {
        int c   = idx / (NR*18);
        int rem = idx - c*(NR*18);
        int r   = rem / 18;
        int col = rem - r*18;
        int y = ty0 - 1 + r, x = tx0 - 1 + col;
        float v = 0.f;
        if ((unsigned)y < Hn && (unsigned)x < Wn) v = inb[(c*Hn + y)*Wn + x];
        s_in[c*CIN_STRIDE + r*RS + col] = v;
    }

    const int og    = tid >> 5;        // 0..15 (warp-uniform)
    const int obase = og << 2;         // 4 och per thread
    const int pg    = tid & 31;
    const int py    = pg >> 2;         // 0..7
    const int pxb   = (pg & 3) << 2;   // 0,4,8,12

    const uint32_t s_in_sh = (uint32_t)__cvta_generic_to_shared(s_in)
                           + (uint32_t)(py*RS + pxb)*4u;
    const uint32_t s_w_sh  = (uint32_t)__cvta_generic_to_shared(s_w)
                           + (uint32_t)obase*4u;

    u64 accF[2][4], accD[2][4];
#pragma unroll
    for (int u = 0; u < 2; ++u)
#pragma unroll
        for (int j = 0; j < 4; ++j) { accF[u][j] = 0ull; if (DUAL) accD[u][j] = 0ull; }

    for (int cc0 = 0; cc0 < Cn; cc0 += WCHUNK) {
        __syncthreads();
        // stage weight chunk: s_w[(ci*9+kk)*WSTRIDE + o] = w[o][cc0+ci][kk]
        // (coalesced global reads: 144 contiguous floats per o)
#pragma unroll 1
        for (int idx = tid; idx < WCHUNK*9*Cn; idx += 512) {
            int o = idx / (WCHUNK*9);
            int r = idx - o*(WCHUNK*9);    // ci*9+kk
            s_w[r*WSTRIDE + o] = w[o*(Cn*9) + cc0*9 + r];
        }
        __syncthreads();

        uint32_t a_in = s_in_sh + (uint32_t)cc0*(CIN_STRIDE*4);
        uint32_t a_w  = s_w_sh;
#pragma unroll 1
        for (int ci = 0; ci < WCHUNK; ++ci) {
            u64 p[2][4];
#pragma unroll
            for (int ky = 0; ky < 3; ++ky) {
                float r0,r1,r2,r3,r4,r5;
                lds4(r0,r1,r2,r3, a_in + ky*(RS*4));
                lds2(r4,r5,       a_in + ky*(RS*4) + 16);
                u64 iv[6];
                iv[0]=dup2(r0); iv[1]=dup2(r1); iv[2]=dup2(r2);
                iv[3]=dup2(r3); iv[4]=dup2(r4); iv[5]=dup2(r5);
#pragma unroll
                for (int kx = 0; kx < 3; ++kx) {
                    u64 w0, w1;
                    ldsw(w0, w1, a_w + (ky*3+kx)*(WSTRIDE*4));
                    if (ky == 0 && kx == 0) {
#pragma unroll
                        for (int j = 0; j < 4; ++j) {
                            p[0][j] = fmul2(w0, iv[j]);
                            p[1][j] = fmul2(w1, iv[j]);
                        }
                    } else {
#pragma unroll
                        for (int j = 0; j < 4; ++j) {
                            p[0][j] = ffma2(w0, iv[kx+j], p[0][j]);
                            p[1][j] = ffma2(w1, iv[kx+j], p[1][j]);
                        }
                    }
                }
            }
            if (DUAL) {
                u64 m2 = dup2(s_md[cc0+ci]);
#pragma unroll
                for (int u = 0; u < 2; ++u)
#pragma unroll
                    for (int j = 0; j < 4; ++j) {
                        accF[u][j] = fadd2(accF[u][j], p[u][j]);
                        accD[u][j] = ffma2(m2, p[u][j], accD[u][j]);
                    }
            } else {
#pragma unroll
                for (int u = 0; u < 2; ++u)
#pragma unroll
                    for (int j = 0; j < 4; ++j)
                        accF[u][j] = fadd2(accF[u][j], p[u][j]);
            }
            a_in += CIN_STRIDE*4;
            a_w  += 9*WSTRIDE*4;
        }
    }

    // fused gating + ReLU epilogue
    const float4 spv = *(const float4*)(spa + b*HWn + (ty0+py)*Wn + tx0 + pxb);
    const float sp[4] = {spv.x, spv.y, spv.z, spv.w};
    float* outp_ = out + b*IMG + (ty0+py)*Wn + tx0 + pxb;

#pragma unroll
    for (int u = 0; u < 2; ++u) {
        float f0[4], f1[4], d0[4], d1[4];
#pragma unroll
        for (int j = 0; j < 4; ++j) {
            unpk(accF[u][j], f0[j], f1[j]);
            if (DUAL) unpk(accD[u][j], d0[j], d1[j]);
        }
        const int o0 = obase + 2*u;
        const float md0 = s_md[o0],   ms0 = s_ms[o0];
        const float md1 = s_md[o0+1], ms1 = s_ms[o0+1];
        float t0[4], t1[4];
#pragma unroll
        for (int j = 0; j < 4; ++j) {
            float a, c;
            if (!DUAL) {
                a = f0[j] * (ms0*sp[j] + md0);
                c = f1[j] * (ms1*sp[j] + md1);
            } else {
                a = d0[j]*md0*(1.f - sp[j]) + f0[j]*sp[j];
                c = d1[j]*md1*(1.f - sp[j]) + f1[j]*sp[j];
            }
            t0[j] = fmaxf(a, 0.f);
            t1[j] = fmaxf(c, 0.f);
        }
        *(float4*)(outp_ +  o0   *HWn) = make_float4(t0[0],t0[1],t0[2],t0[3]);
        *(float4*)(outp_ + (o0+1)*HWn) = make_float4(t1[0],t1[1],t1[2],t1[3]);
    }
}

// ---------------------------------------------------------------------------
// Final 1x1 conv over the concat (fp32x2): out[b,o,p] = bc[o] + sum_k wc*cat
// Block: 64 o x 256 px. 256 threads: thread = 8 o (4 pairs) x 8 px.
// ---------------------------------------------------------------------------
#define WCS 68
__global__ void __launch_bounds__(256)
final_kernel(const float* __restrict__ wc, const float* __restrict__ bc,
             float* __restrict__ outp)
{
    __shared__ float s_wc[16*WCS];   // [kk][o] padded
    __shared__ float s_cat[16*256];  // [kk][px]

    const int blk = blockIdx.x;
    const int b   = blk >> 6;
    const int p0  = (blk & 63) * 256;
    const int tid = threadIdx.x;
    const int og  = tid >> 5;
    const int pg  = tid & 31;
    const int obase = og << 3;

    const uint32_t wc_sh = (uint32_t)__cvta_generic_to_shared(s_wc)
                         + (uint32_t)obase*4u;

    u64 acc[4][8];
#pragma unroll
    for (int u = 0; u < 4; ++u)
#pragma unroll
        for (int j = 0; j < 8; ++j) acc[u][j] = 0ull;

    for (int k0 = 0; k0 < 256; k0 += 16) {
        __syncthreads();
        // coalesced wc staging: 16 contiguous floats per o
        for (int idx = tid; idx < 16*64; idx += 256) {
            int o = idx >> 4, kk = idx & 15;
            s_wc[kk*WCS + o] = wc[o*256 + k0 + kk];
        }
        const float* src = g_feat[k0 >> 6] + (b*Cn + (k0 & 63))*HWn + p0;
        for (int idx = tid; idx < 16*256; idx += 256) {
            int kk = idx >> 8, px = idx & 255;
            s_cat[kk*256 + px] = src[kk*HWn + px];
        }
        __syncthreads();
#pragma unroll
        for (int kk = 0; kk < 16; ++kk) {
            u64 w01, w23, w45, w67;
            ldsw(w01, w23, wc_sh + kk*(WCS*4));
            ldsw(w45, w67, wc_sh + kk*(WCS*4) + 16);
            u64 cv[8];
#pragma unroll
            for (int j = 0; j < 8; ++j)
                cv[j] = dup2(s_cat[kk*256 + pg + 32*j]);
#pragma unroll
            for (int j = 0; j < 8; ++j) {
                acc[0][j] = ffma2(w01, cv[j], acc[0][j]);
                acc[1][j] = ffma2(w23, cv[j], acc[1][j]);
                acc[2][j] = ffma2(w45, cv[j], acc[2][j]);
                acc[3][j] = ffma2(w67, cv[j], acc[3][j]);
            }
        }
    }

#pragma unroll
    for (int u = 0; u < 4; ++u) {
        const int o0 = obase + 2*u;
        const float b0 = bc[o0], b1 = bc[o0+1];
        float* q0 = outp + (b*Cn + o0  )*HWn + p0 + pg;
        float* q1 = outp + (b*Cn + o0+1)*HWn + p0 + pg;
#pragma unroll
        for (int j = 0; j < 8; ++j) {
            float a, c;
            unpk(acc[u][j], a, c);
            q0[32*j] = a + b0;
            q1[32*j] = c + b1;
        }
    }
}

// ---------------------------------------------------------------------------
extern "C" void kernel_launch(void* const* d_in, const int* in_sizes, int n_in,
                              void* d_out, int out_size)
{
    const float* x0  = (const float*)d_in[0];
    const float* spa = (const float*)d_in[1];
    const float* gum = (const float*)d_in[2];
    const float* par = (const float*)d_in[3];
    const float* w0  = (const float*)d_in[4];
    const float* w1  = (const float*)d_in[5];
    const float* w2  = (const float*)d_in[6];
    const float* w3  = (const float*)d_in[7];
    const float* wc  = (const float*)d_in[8];
    const float* bc  = (const float*)d_in[9];

    float* outp = (float*)d_out;
    float* tail = outp + (out_size - 512);   // ch_mask (1,64,4,2) after main out

    cudaFuncSetAttribute(conv_kernel<false>,
                         cudaFuncAttributeMaxDynamicSharedMemorySize, SMEM_CONV);
    cudaFuncSetAttribute(conv_kernel<true>,
                         cudaFuncAttributeMaxDynamicSharedMemorySize, SMEM_CONV);

    mask_kernel<<<1, 64>>>(gum, par, tail);

    dim3 grid(Wn/TW, Hn/TH, Bn);   // 8 x 16 x 16 = 2048 blocks
    conv_kernel<false><<<grid, 512, SMEM_CONV>>>(x0, w0, spa, 0);
    conv_kernel<true ><<<grid, 512, SMEM_CONV>>>(x0, w1, spa, 1);
    conv_kernel<true ><<<grid, 512, SMEM_CONV>>>(x0, w2, spa, 2);
    conv_kernel<true ><<<grid, 512, SMEM_CONV>>>(x0, w3, spa, 3);

    final_kernel<<<Bn*64, 256>>>(wc, bc, outp);
}